// round 13
// baseline (speedup 1.0000x reference)
#include <cuda_runtime.h>
#include <cuda_fp16.h>
#include <cstdint>

// ------------------------- problem constants -------------------------
#define CC 256
#define LL 8192
#define BB 32
#define TL 64            // positions per CTA (and per warp)
#define KC 32            // K chunk
#define NCHUNK 8
#define NSTAGE 3

// ------------------------- smem layout (bytes) -----------------------
#define XOFF(s)  ((s) * 4096)       // x fp16: 32 k-rows x 128B (swizzled), 3 slots
#define SBIAS    12288              // 256 floats
#define SQBUF    13312              // 4 x 64 floats
#define SCALE    14336              // 64 floats
#define SMEM_BYTES 14592

// ------------------------- device scratch ----------------------------
// W' fp16 pairs in exact A-fragment order (per 32-k chunk):
// idx = (((kc*2+ks)*16 + mb)*32 + lane)*4 + reg   (each u32 = 2 fp16, k-pair)
__device__ __align__(16) unsigned g_Wf[CC * CC / 2];
__device__ float g_bias[CC];

// ------------------------- helpers -----------------------------------
__device__ __forceinline__ uint32_t smem_u32(const void* p) {
    uint32_t a;
    asm("{ .reg .u64 t; cvta.to.shared.u64 t, %1; cvt.u32.u64 %0, t; }"
        : "=r"(a) : "l"(p));
    return a;
}
__device__ __forceinline__ uint32_t pkh2(float a, float b) {
    __half2 h = __floats2half2_rn(a, b);
    return *reinterpret_cast<uint32_t*>(&h);
}
__device__ __forceinline__ void ldsm_x2t(uint32_t* r, uint32_t addr) {
    asm volatile("ldmatrix.sync.aligned.m8n8.x2.trans.shared.b16 {%0,%1}, [%2];"
                 : "=r"(r[0]), "=r"(r[1]) : "r"(addr));
}
__device__ __forceinline__ void mma_f16(float* d, const uint32_t* a, const uint32_t* b) {
    asm volatile(
        "mma.sync.aligned.m16n8k16.row.col.f32.f16.f16.f32 "
        "{%0,%1,%2,%3}, {%4,%5,%6,%7}, {%8,%9}, {%0,%1,%2,%3};"
        : "+f"(d[0]), "+f"(d[1]), "+f"(d[2]), "+f"(d[3])
        : "r"(a[0]), "r"(a[1]), "r"(a[2]), "r"(a[3]), "r"(b[0]), "r"(b[1]));
}

// ------------------------- prep kernel -------------------------------
__global__ void fold_kernel(const float* __restrict__ W, const float* __restrict__ b,
                            const float* __restrict__ gamma, const float* __restrict__ beta,
                            const float* __restrict__ mean, const float* __restrict__ var) {
    int o = blockIdx.x;
    int j = threadIdx.x;          // c pair: c = 2j, 2j+1
    float inv = gamma[o] * rsqrtf(var[o] + 1e-5f);
    int c = 2 * j;
    float w0 = W[o * CC + c] * inv;
    float w1 = W[o * CC + c + 1] * inv;
    int kc = c >> 5;
    int ks = (c >> 4) & 1;
    int kl = c & 15;
    int mb = o >> 4;
    int lane = (o & 7) * 4 + ((kl >> 1) & 3);
    int reg  = ((o >> 3) & 1) + 2 * (kl >> 3);
    g_Wf[(((kc * 2 + ks) * 16 + mb) * 32 + lane) * 4 + reg] = pkh2(w0, w1);
    if (j == 0) g_bias[o] = b[o] * inv + beta[o] - mean[o] * inv;
}

// ------------------------- main kernel -------------------------------
// 128 threads, 4 warps. Each warp: 64 oc x ALL 64 pos (acc[4][8][4]).
// 2 CTAs/SM. Tile 256 oc x 64 pos; K in 8 chunks of 32.
// A-frags direct LDG (L1-hot, 2x reuse vs R12); x via LDG->pkh2->STS 3-ring.
extern "C" __global__ void __launch_bounds__(128, 2)
caps_kernel(const float* __restrict__ x, float* __restrict__ out) {
    extern __shared__ char smem[];
    const uint32_t sbu = smem_u32(smem);
    const int t    = threadIdx.x;
    const int lane = t & 31;
    const int wm   = t >> 5;            // warp = m-slice
    const int m0   = wm * 64;
    const int bb   = blockIdx.y;
    const int l0   = blockIdx.x * TL;

    ((float*)(smem + SBIAS))[t]       = g_bias[t];
    ((float*)(smem + SBIAS))[t + 128] = g_bias[t + 128];

    const float* xg = x + (size_t)bb * CC * LL + l0;

    float acc[4][8][4];
    #pragma unroll
    for (int i = 0; i < 4; i++)
        #pragma unroll
        for (int j = 0; j < 8; j++)
            #pragma unroll
            for (int q = 0; q < 4; q++) acc[i][j][q] = 0.0f;

    // ---- x staging: 2 units/thread; unit v: row xk=v>>3, seg xp=v&7 ----
    float4 xv[2][2];
    auto ldg_x = [&](int kc) {
        #pragma unroll
        for (int it = 0; it < 2; it++) {
            int v = t + it * 128;
            int xk = v >> 3, xp = v & 7;
            const float* s = xg + (size_t)(kc * KC + xk) * LL + xp * 8;
            xv[it][0] = __ldg((const float4*)s);
            xv[it][1] = __ldg((const float4*)(s + 4));
        }
    };
    auto stage_x = [&](int st) {
        #pragma unroll
        for (int it = 0; it < 2; it++) {
            int v = t + it * 128;
            int xk = v >> 3, xp = v & 7;
            uint32_t off = (uint32_t)(xk * 128 + ((xp ^ (xk & 7)) << 4));
            uint4 u;
            u.x = pkh2(xv[it][0].x, xv[it][0].y);
            u.y = pkh2(xv[it][0].z, xv[it][0].w);
            u.z = pkh2(xv[it][1].x, xv[it][1].y);
            u.w = pkh2(xv[it][1].z, xv[it][1].w);
            *(uint4*)(smem + XOFF(st) + off) = u;
        }
    };

    // ---- fragment loads ----------------------------------------------
    const uint4* Wg0 = (const uint4*)g_Wf;       // 512 uint4 per k16 step
    auto load_af = [&](uint32_t (*af)[4], int kc, int ks16) {
        const uint4* Wg = Wg0 + (size_t)(kc * 2 + ks16) * 512 + wm * 128 + lane;
        #pragma unroll
        for (int i = 0; i < 4; i++) {
            uint4 v = __ldg(Wg + i * 32);
            af[i][0] = v.x; af[i][1] = v.y; af[i][2] = v.z; af[i][3] = v.w;
        }
    };
    auto load_bf = [&](uint32_t (*bf)[2], int st, int ks16) {
        const uint32_t Xb = sbu + XOFF(st);
        int row = ks16 * 16 + (lane & 15);
        #pragma unroll
        for (int j = 0; j < 8; j++)
            ldsm_x2t(bf[j], Xb + (uint32_t)(row * 128
                               + ((j ^ (lane & 7)) << 4)));
    };
    auto mma16 = [&](uint32_t (*af)[4], uint32_t (*bf)[2]) {
        #pragma unroll
        for (int i = 0; i < 4; i++)
            #pragma unroll
            for (int j = 0; j < 8; j++)
                mma_f16(acc[i][j], af[i], bf[j]);
    };

    // ---- pipeline: 3-ring, 1 barrier/chunk, frag double-buffer --------
    ldg_x(0); stage_x(0);
    ldg_x(1); stage_x(1);

    uint32_t af0[4][4], af1[4][4], bf0[8][2], bf1[8][2];
    for (int k = 0; k < NCHUNK; k++) {
        const int st = k % NSTAGE;
        if (k + 2 < NCHUNK) ldg_x(k + 2);
        __syncthreads();                   // stage(k) visible
        load_bf(bf0, st, 0);
        load_af(af0, k, 0);
        load_bf(bf1, st, 1);               // prefetch ks1 before ks0 MMA
        load_af(af1, k, 1);
        mma16(af0, bf0);
        if (k + 2 < NCHUNK) stage_x((k + 2) % NSTAGE);
        mma16(af1, bf1);
    }

    // ---- epilogue: bias + squash + direct store ------------------------
    const float* sbias = (const float*)(smem + SBIAS);
    const int gid = lane >> 2;
    const int qid = lane & 3;

    float sqA[8], sqB[8];
    #pragma unroll
    for (int j = 0; j < 8; j++) { sqA[j] = 0.0f; sqB[j] = 0.0f; }

    #pragma unroll
    for (int i = 0; i < 4; i++) {
        int r0 = m0 + i * 16 + gid;
        float b0 = sbias[r0], b1 = sbias[r0 + 8];
        #pragma unroll
        for (int j = 0; j < 8; j++) {
            float y0 = acc[i][j][0] + b0;
            float y1 = acc[i][j][1] + b0;
            float y2 = acc[i][j][2] + b1;
            float y3 = acc[i][j][3] + b1;
            acc[i][j][0] = y0; acc[i][j][1] = y1;
            acc[i][j][2] = y2; acc[i][j][3] = y3;
            sqA[j] += y0 * y0 + y2 * y2;
            sqB[j] += y1 * y1 + y3 * y3;
        }
    }
    #pragma unroll
    for (int j = 0; j < 8; j++) {
        #pragma unroll
        for (int m = 4; m < 32; m <<= 1) {
            sqA[j] += __shfl_xor_sync(0xffffffffu, sqA[j], m);
            sqB[j] += __shfl_xor_sync(0xffffffffu, sqB[j], m);
        }
    }
    float* sqb = (float*)(smem + SQBUF);
    if (lane < 4) {
        #pragma unroll
        for (int j = 0; j < 8; j++) {
            int col = j * 8 + lane * 2;
            sqb[wm * 64 + col]     = sqA[j];
            sqb[wm * 64 + col + 1] = sqB[j];
        }
    }
    __syncthreads();
    if (t < 64) {
        float s = sqb[t] + sqb[64 + t] + sqb[128 + t] + sqb[192 + t];
        float n = sqrtf(s);
        ((float*)(smem + SCALE))[t] = s / ((1.0f + s) * (n + 1e-8f));
    }
    __syncthreads();

    const float* scl = (const float*)(smem + SCALE);
    float* og = out + ((size_t)bb * LL + l0) * CC;
    #pragma unroll
    for (int j = 0; j < 8; j++) {
        int c0 = j * 8 + qid * 2;            // position
        float s0 = scl[c0], s1 = scl[c0 + 1];
        float* p0 = og + (size_t)c0 * CC;
        float* p1 = og + (size_t)(c0 + 1) * CC;
        #pragma unroll
        for (int i = 0; i < 4; i++) {
            int r0 = m0 + i * 16 + gid;      // channel
            p0[r0]     = acc[i][j][0] * s0;
            p1[r0]     = acc[i][j][1] * s1;
            p0[r0 + 8] = acc[i][j][2] * s0;
            p1[r0 + 8] = acc[i][j][3] * s1;
        }
    }
}

// ------------------------- launch ------------------------------------
extern "C" void kernel_launch(void* const* d_in, const int* in_sizes, int n_in,
                              void* d_out, int out_size) {
    const float* x     = (const float*)d_in[0];
    const float* W     = (const float*)d_in[1];
    const float* b     = (const float*)d_in[2];
    const float* gamma = (const float*)d_in[3];
    const float* beta  = (const float*)d_in[4];
    const float* mean  = (const float*)d_in[5];
    const float* var   = (const float*)d_in[6];
    float* out = (float*)d_out;

    fold_kernel<<<CC, 128>>>(W, b, gamma, beta, mean, var);

    cudaFuncSetAttribute(caps_kernel,
                         cudaFuncAttributeMaxDynamicSharedMemorySize, SMEM_BYTES);
    dim3 grid(LL / TL, BB);
    caps_kernel<<<grid, 128, SMEM_BYTES>>>(x, out);
}

// round 14
// speedup vs baseline: 1.0315x; 1.0315x over previous
#include <cuda_runtime.h>
#include <cuda_fp16.h>
#include <cstdint>

// ------------------------- problem constants -------------------------
#define CC 256
#define LL 8192
#define BB 32
#define TL 32            // positions per CTA
#define NKS 16           // k16 steps (full K = 256)

// ------------------------- smem layout (bytes) -----------------------
#define XTILE    0                  // x fp16: 256 k-rows x 64B (swizzled) = 16KB
#define SBIAS    16384              // 256 floats
#define SQBUF    17408              // 4 x 32 floats
#define SCALE    17920              // 32 floats
#define SMEM_BYTES 18048

// ------------------------- device scratch ----------------------------
// W' fp16 pairs in exact A-fragment order (per k16 step):
// idx = ((ks*16 + mb)*32 + lane)*4 + reg   (each u32 = 2 fp16, k-pair)
__device__ __align__(16) unsigned g_Wf[CC * CC / 2];
__device__ float g_bias[CC];

// ------------------------- helpers -----------------------------------
__device__ __forceinline__ uint32_t smem_u32(const void* p) {
    uint32_t a;
    asm("{ .reg .u64 t; cvta.to.shared.u64 t, %1; cvt.u32.u64 %0, t; }"
        : "=r"(a) : "l"(p));
    return a;
}
__device__ __forceinline__ uint32_t pkh2(float a, float b) {
    __half2 h = __floats2half2_rn(a, b);
    return *reinterpret_cast<uint32_t*>(&h);
}
__device__ __forceinline__ void ldsm_x2t(uint32_t* r, uint32_t addr) {
    asm volatile("ldmatrix.sync.aligned.m8n8.x2.trans.shared.b16 {%0,%1}, [%2];"
                 : "=r"(r[0]), "=r"(r[1]) : "r"(addr));
}
__device__ __forceinline__ void mma_f16(float* d, const uint32_t* a, const uint32_t* b) {
    asm volatile(
        "mma.sync.aligned.m16n8k16.row.col.f32.f16.f16.f32 "
        "{%0,%1,%2,%3}, {%4,%5,%6,%7}, {%8,%9}, {%0,%1,%2,%3};"
        : "+f"(d[0]), "+f"(d[1]), "+f"(d[2]), "+f"(d[3])
        : "r"(a[0]), "r"(a[1]), "r"(a[2]), "r"(a[3]), "r"(b[0]), "r"(b[1]));
}

// ------------------------- prep kernel -------------------------------
// Fold BN into W, convert fp16, emit A-fragment-order image.
// (ks here = global k16 step 0..15; same layout as before with kc*2+ks16.)
__global__ void fold_kernel(const float* __restrict__ W, const float* __restrict__ b,
                            const float* __restrict__ gamma, const float* __restrict__ beta,
                            const float* __restrict__ mean, const float* __restrict__ var) {
    int o = blockIdx.x;
    int j = threadIdx.x;          // c pair: c = 2j, 2j+1
    float inv = gamma[o] * rsqrtf(var[o] + 1e-5f);
    int c = 2 * j;
    float w0 = W[o * CC + c] * inv;
    float w1 = W[o * CC + c + 1] * inv;
    int ks = c >> 4;              // global k16 step 0..15
    int kl = c & 15;
    int mb = o >> 4;
    int lane = (o & 7) * 4 + ((kl >> 1) & 3);
    int reg  = ((o >> 3) & 1) + 2 * (kl >> 3);
    g_Wf[((ks * 16 + mb) * 32 + lane) * 4 + reg] = pkh2(w0, w1);
    if (j == 0) g_bias[o] = b[o] * inv + beta[o] - mean[o] * inv;
}

// ------------------------- main kernel -------------------------------
// 128 threads, 4 warps (each: 64 oc x all 32 pos). 4 CTAs/SM (16 warps).
// Full-K x tile staged once in SMEM; mainloop has ZERO barriers:
// per k16 step, af via LDG.128 from L1-hot W image, bf via ldmatrix.
extern "C" __global__ void __launch_bounds__(128, 4)
caps_kernel(const float* __restrict__ x, float* __restrict__ out) {
    extern __shared__ char smem[];
    const uint32_t sbu = smem_u32(smem);
    const int t    = threadIdx.x;
    const int lane = t & 31;
    const int wm   = t >> 5;            // warp = m-slice
    const int m0   = wm * 64;
    const int bb   = blockIdx.y;
    const int l0   = blockIdx.x * TL;

    ((float*)(smem + SBIAS))[t]       = g_bias[t];
    ((float*)(smem + SBIAS))[t + 128] = g_bias[t + 128];

    const float* xg = x + (size_t)bb * CC * LL + l0;

    // ---- prologue: stage full x tile (256 k-rows x 32 pos fp16) --------
    // thread: rows r = (t>>2) + 32*pass, seg p8 = t&3 (8 pos = 16B fp16).
    {
        const int r0 = t >> 2;
        const int p8 = t & 3;
        #pragma unroll
        for (int pass = 0; pass < 8; pass++) {
            int r = r0 + pass * 32;
            const float* s = xg + (size_t)r * LL + p8 * 8;
            float4 a = __ldg((const float4*)s);
            float4 c = __ldg((const float4*)(s + 4));
            uint4 u;
            u.x = pkh2(a.x, a.y); u.y = pkh2(a.z, a.w);
            u.z = pkh2(c.x, c.y); u.w = pkh2(c.z, c.w);
            uint32_t off = (uint32_t)(r * 64 + ((p8 ^ ((r >> 1) & 3)) << 4));
            *(uint4*)(smem + XTILE + off) = u;
        }
    }
    __syncthreads();                    // the ONLY barrier before epilogue

    float acc[4][4][4];
    #pragma unroll
    for (int i = 0; i < 4; i++)
        #pragma unroll
        for (int j = 0; j < 4; j++)
            #pragma unroll
            for (int q = 0; q < 4; q++) acc[i][j][q] = 0.0f;

    // ---- fragment loads ------------------------------------------------
    const uint4* Wg0 = (const uint4*)g_Wf;       // 512 uint4 per k16 step
    auto load_af = [&](uint32_t (*af)[4], int ks) {
        const uint4* Wg = Wg0 + (size_t)ks * 512 + wm * 128 + lane;
        #pragma unroll
        for (int i = 0; i < 4; i++) {
            uint4 v = __ldg(Wg + i * 32);
            af[i][0] = v.x; af[i][1] = v.y; af[i][2] = v.z; af[i][3] = v.w;
        }
    };
    auto load_bf = [&](uint32_t (*bf)[2], int ks) {
        int row = ks * 16 + (lane & 15);
        uint32_t base = sbu + XTILE + (uint32_t)(row * 64);
        uint32_t sw   = (uint32_t)((row >> 1) & 3);
        #pragma unroll
        for (int j = 0; j < 4; j++)
            ldsm_x2t(bf[j], base + ((j ^ sw) << 4));
    };
    auto mma16 = [&](uint32_t (*af)[4], uint32_t (*bf)[2]) {
        #pragma unroll
        for (int i = 0; i < 4; i++)
            #pragma unroll
            for (int j = 0; j < 4; j++)
                mma_f16(acc[i][j], af[i], bf[j]);
    };

    // ---- barrier-free mainloop: 16 k16 steps, double-buffered frags ----
    uint32_t af0[4][4], af1[4][4], bf0[4][2], bf1[4][2];
    load_bf(bf0, 0);
    load_af(af0, 0);
    #pragma unroll
    for (int ks = 0; ks < NKS; ks += 2) {
        if (ks + 1 < NKS) { load_bf(bf1, ks + 1); load_af(af1, ks + 1); }
        mma16(af0, bf0);
        if (ks + 2 < NKS) { load_bf(bf0, ks + 2); load_af(af0, ks + 2); }
        mma16(af1, bf1);
    }

    // ---- epilogue: bias + squash + direct store --------------------------
    const float* sbias = (const float*)(smem + SBIAS);
    const int gid = lane >> 2;
    const int qid = lane & 3;

    float sqA[4], sqB[4];
    #pragma unroll
    for (int j = 0; j < 4; j++) { sqA[j] = 0.0f; sqB[j] = 0.0f; }

    #pragma unroll
    for (int i = 0; i < 4; i++) {
        int r0 = m0 + i * 16 + gid;
        float b0 = sbias[r0], b1 = sbias[r0 + 8];
        #pragma unroll
        for (int j = 0; j < 4; j++) {
            float y0 = acc[i][j][0] + b0;
            float y1 = acc[i][j][1] + b0;
            float y2 = acc[i][j][2] + b1;
            float y3 = acc[i][j][3] + b1;
            acc[i][j][0] = y0; acc[i][j][1] = y1;
            acc[i][j][2] = y2; acc[i][j][3] = y3;
            sqA[j] += y0 * y0 + y2 * y2;
            sqB[j] += y1 * y1 + y3 * y3;
        }
    }
    #pragma unroll
    for (int j = 0; j < 4; j++) {
        #pragma unroll
        for (int m = 4; m < 32; m <<= 1) {
            sqA[j] += __shfl_xor_sync(0xffffffffu, sqA[j], m);
            sqB[j] += __shfl_xor_sync(0xffffffffu, sqB[j], m);
        }
    }
    float* sqb = (float*)(smem + SQBUF);
    if (lane < 4) {
        #pragma unroll
        for (int j = 0; j < 4; j++) {
            int col = j * 8 + lane * 2;
            sqb[wm * 32 + col]     = sqA[j];
            sqb[wm * 32 + col + 1] = sqB[j];
        }
    }
    __syncthreads();
    if (t < 32) {
        float s = sqb[t] + sqb[32 + t] + sqb[64 + t] + sqb[96 + t];
        float n = sqrtf(s);
        ((float*)(smem + SCALE))[t] = s / ((1.0f + s) * (n + 1e-8f));
    }
    __syncthreads();

    const float* scl = (const float*)(smem + SCALE);
    float* og = out + ((size_t)bb * LL + l0) * CC;
    #pragma unroll
    for (int j = 0; j < 4; j++) {
        int c0 = j * 8 + qid * 2;            // position
        float s0 = scl[c0], s1 = scl[c0 + 1];
        float* p0 = og + (size_t)c0 * CC;
        float* p1 = og + (size_t)(c0 + 1) * CC;
        #pragma unroll
        for (int i = 0; i < 4; i++) {
            int r0 = m0 + i * 16 + gid;      // channel
            p0[r0]     = acc[i][j][0] * s0;
            p1[r0]     = acc[i][j][1] * s1;
            p0[r0 + 8] = acc[i][j][2] * s0;
            p1[r0 + 8] = acc[i][j][3] * s1;
        }
    }
}

// ------------------------- launch ------------------------------------
extern "C" void kernel_launch(void* const* d_in, const int* in_sizes, int n_in,
                              void* d_out, int out_size) {
    const float* x     = (const float*)d_in[0];
    const float* W     = (const float*)d_in[1];
    const float* b     = (const float*)d_in[2];
    const float* gamma = (const float*)d_in[3];
    const float* beta  = (const float*)d_in[4];
    const float* mean  = (const float*)d_in[5];
    const float* var   = (const float*)d_in[6];
    float* out = (float*)d_out;

    fold_kernel<<<CC, 128>>>(W, b, gamma, beta, mean, var);

    cudaFuncSetAttribute(caps_kernel,
                         cudaFuncAttributeMaxDynamicSharedMemorySize, SMEM_BYTES);
    dim3 grid(LL / TL, BB);
    caps_kernel<<<grid, 128, SMEM_BYTES>>>(x, out);
}